// round 1
// baseline (speedup 1.0000x reference)
#include <cuda_runtime.h>
#include <cuda_bf16.h>
#include <math.h>

// Problem constants (fixed shapes)
#define NN   4096      // N = V*B
#define BB   2048      // batch
#define VV   2         // views
#define DD   256       // feature dim
#define CC   1000      // classes
#define TEMP 0.07f

// Scratch (no cudaMalloc allowed)
__device__ float g_cf[NN * DD];   // normalized, view-major stacked features [N, D]
__device__ float g_mod[BB];       // focal modulation per sample
__device__ float g_S[NN];         // sum exp(l - M) over j != i
__device__ float g_P[NN];         // sum over positives of (l - M)
__device__ float g_cnt[NN];       // positive counts

// ---------------------------------------------------------------------------
// K0: normalize rows + view-major restack + zero accumulators
// features [B, V, D] -> g_cf[v*B + b][:]
// one warp per output row
// ---------------------------------------------------------------------------
__global__ void norm_kernel(const float* __restrict__ feats) {
    int gw   = (blockIdx.x * blockDim.x + threadIdx.x) >> 5;
    int lane = threadIdx.x & 31;
    if (gw >= NN) return;
    int b = gw & (BB - 1);
    int v = gw >> 11;

    const float4* src = reinterpret_cast<const float4*>(feats + (size_t)(b * VV + v) * DD);
    float4 x0 = src[lane];
    float4 x1 = src[lane + 32];

    float ss = x0.x * x0.x + x0.y * x0.y + x0.z * x0.z + x0.w * x0.w
             + x1.x * x1.x + x1.y * x1.y + x1.z * x1.z + x1.w * x1.w;
#pragma unroll
    for (int o = 16; o > 0; o >>= 1) ss += __shfl_xor_sync(0xffffffffu, ss, o);
    float inv = rsqrtf(ss);

    float4 y0 = make_float4(x0.x * inv, x0.y * inv, x0.z * inv, x0.w * inv);
    float4 y1 = make_float4(x1.x * inv, x1.y * inv, x1.z * inv, x1.w * inv);
    float4* dst = reinterpret_cast<float4*>(g_cf + (size_t)gw * DD);
    dst[lane]      = y0;
    dst[lane + 32] = y1;

    if (lane == 0) {   // zero accumulators every replay (graph-safe)
        g_S[gw] = 0.f; g_P[gw] = 0.f; g_cnt[gw] = 0.f;
    }
}

// ---------------------------------------------------------------------------
// K1: focal modulation per sample: mod = (1 - exp(log_softmax(preds)[label]))^2
// one block (128 threads) per sample b
// ---------------------------------------------------------------------------
__device__ __forceinline__ float warp_max(float v) {
#pragma unroll
    for (int o = 16; o > 0; o >>= 1) v = fmaxf(v, __shfl_xor_sync(0xffffffffu, v, o));
    return v;
}
__device__ __forceinline__ float warp_sum(float v) {
#pragma unroll
    for (int o = 16; o > 0; o >>= 1) v += __shfl_xor_sync(0xffffffffu, v, o);
    return v;
}

__global__ void mod_kernel(const float* __restrict__ preds, const int* __restrict__ labels) {
    __shared__ float sh4[4];
    int b = blockIdx.x, t = threadIdx.x, lane = t & 31, w = t >> 5;
    const float* row = preds + (size_t)b * CC;

    float mx = -1e30f;
    for (int c = t; c < CC; c += 128) mx = fmaxf(mx, row[c]);
    mx = warp_max(mx);
    if (lane == 0) sh4[w] = mx;
    __syncthreads();
    mx = fmaxf(fmaxf(sh4[0], sh4[1]), fmaxf(sh4[2], sh4[3]));
    __syncthreads();

    float s = 0.f;
    for (int c = t; c < CC; c += 128) s += __expf(row[c] - mx);
    s = warp_sum(s);
    if (lane == 0) sh4[w] = s;
    __syncthreads();

    if (t == 0) {
        float ssum = sh4[0] + sh4[1] + sh4[2] + sh4[3];
        float nll  = row[labels[b]] - mx - logf(ssum);  // log p_t
        float pt   = __expf(nll);
        float om   = 1.f - pt;
        g_mod[b]   = om * om;    // GAMMA = 2
    }
}

// ---------------------------------------------------------------------------
// K2: fused similarity GEMM + row reductions.
// Block = 64 rows x 1024-column strip. Grid (64, 4). 256 threads.
// Shared tiles stored k-major: As[256][68], Bs[64][68] (pad=4 floats).
// Microtile 4x4 per thread: per-k = 2x LDS.128 + 16 FFMA.
// Shift M = 1/T applied analytically (cancels exactly vs reference's row max).
// ---------------------------------------------------------------------------
#define WPAD 68
#define K2_SMEM ((256 * WPAD + 64 * WPAD) * 4)

__global__ void __launch_bounds__(256) main_kernel(const int* __restrict__ labels) {
    extern __shared__ float sh[];
    float* As = sh;                 // [256][WPAD] k-major, full D for 64 rows
    float* Bs = sh + 256 * WPAD;    // [64][WPAD]  k-major, BK=64 chunk for 64 cols
    __shared__ float sS[64], sP[64], sC[64];
    __shared__ int   cl[64];

    const int tid = threadIdx.x;
    const int tr = tid >> 4;        // 0..15 -> rows tr*4..tr*4+3
    const int tc = tid & 15;        // 0..15 -> cols tc*4..tc*4+3
    const int i0 = blockIdx.x * 64;
    const int jbase = blockIdx.y * 1024;

    if (tid < 64) { sS[tid] = 0.f; sP[tid] = 0.f; sC[tid] = 0.f; }

    // Fill As (once): rows i0..i0+63, all 256 k, transposed to k-major.
    {
        int r   = tid >> 2;
        int kq0 = tid & 3;
        const float4* src = reinterpret_cast<const float4*>(g_cf + (size_t)(i0 + r) * DD);
#pragma unroll
        for (int it = 0; it < 16; ++it) {
            int kq = kq0 + (it << 2);
            float4 vv = src[kq];
            int kb = kq << 2;
            As[(kb + 0) * WPAD + r] = vv.x;
            As[(kb + 1) * WPAD + r] = vv.y;
            As[(kb + 2) * WPAD + r] = vv.z;
            As[(kb + 3) * WPAD + r] = vv.w;
        }
    }

    int rl[4];
#pragma unroll
    for (int m = 0; m < 4; ++m) rl[m] = labels[(i0 + tr * 4 + m) & (BB - 1)];

    float s_acc[4] = {0.f, 0.f, 0.f, 0.f};
    float p_acc[4] = {0.f, 0.f, 0.f, 0.f};
    float c_acc[4] = {0.f, 0.f, 0.f, 0.f};

    const float invT = 1.0f / TEMP;

    for (int jt = 0; jt < 16; ++jt) {
        const int j0 = jbase + jt * 64;
        float acc[4][4];
#pragma unroll
        for (int m = 0; m < 4; ++m)
#pragma unroll
            for (int n = 0; n < 4; ++n) acc[m][n] = 0.f;

        for (int kc = 0; kc < 4; ++kc) {
            __syncthreads();
            // fill Bs chunk: cols j0..j0+63, k in [kc*64, kc*64+64)
            {
                int c   = tid >> 2;
                int kq0 = tid & 3;
                const float4* src = reinterpret_cast<const float4*>(
                    g_cf + (size_t)(j0 + c) * DD + kc * 64);
#pragma unroll
                for (int it = 0; it < 4; ++it) {
                    int kq = kq0 + (it << 2);
                    float4 vv = src[kq];
                    int kb = kq << 2;
                    Bs[(kb + 0) * WPAD + c] = vv.x;
                    Bs[(kb + 1) * WPAD + c] = vv.y;
                    Bs[(kb + 2) * WPAD + c] = vv.z;
                    Bs[(kb + 3) * WPAD + c] = vv.w;
                }
            }
            if (kc == 0 && tid < 64) cl[tid] = labels[(j0 + tid) & (BB - 1)];
            __syncthreads();

            const float* Ab = As + kc * 64 * WPAD;
#pragma unroll 8
            for (int k = 0; k < 64; ++k) {
                float4 a = *reinterpret_cast<const float4*>(Ab + k * WPAD + tr * 4);
                float4 b = *reinterpret_cast<const float4*>(Bs + k * WPAD + tc * 4);
                acc[0][0] += a.x * b.x; acc[0][1] += a.x * b.y;
                acc[0][2] += a.x * b.z; acc[0][3] += a.x * b.w;
                acc[1][0] += a.y * b.x; acc[1][1] += a.y * b.y;
                acc[1][2] += a.y * b.z; acc[1][3] += a.y * b.w;
                acc[2][0] += a.z * b.x; acc[2][1] += a.z * b.y;
                acc[2][2] += a.z * b.z; acc[2][3] += a.z * b.w;
                acc[3][0] += a.w * b.x; acc[3][1] += a.w * b.y;
                acc[3][2] += a.w * b.z; acc[3][3] += a.w * b.w;
            }
        }

        // Epilogue for this 64x64 tile: exp-sum / masked-logit-sum / counts
#pragma unroll
        for (int m = 0; m < 4; ++m) {
            const int i = i0 + tr * 4 + m;
#pragma unroll
            for (int n = 0; n < 4; ++n) {
                const int j = j0 + tc * 4 + n;
                float l = acc[m][n] * invT - invT;   // logits - M, M = 1/T
                if (i != j) {
                    s_acc[m] += __expf(l);
                    if (rl[m] == cl[tc * 4 + n]) { p_acc[m] += l; c_acc[m] += 1.f; }
                }
            }
        }
    }

    // Cross-thread (tc) reduction per row via shared atomics, then one global
    // atomic per row per block (4 column-strip blocks contribute per row).
#pragma unroll
    for (int m = 0; m < 4; ++m) {
        atomicAdd(&sS[tr * 4 + m], s_acc[m]);
        atomicAdd(&sP[tr * 4 + m], p_acc[m]);
        atomicAdd(&sC[tr * 4 + m], c_acc[m]);
    }
    __syncthreads();
    if (tid < 64) {
        atomicAdd(&g_S[i0 + tid],   sS[tid]);
        atomicAdd(&g_P[i0 + tid],   sP[tid]);
        atomicAdd(&g_cnt[i0 + tid], sC[tid]);
    }
}

// ---------------------------------------------------------------------------
// K3: per-row loss + mean
// loss_i = -mod[i%B] * (P_i/cnt_i - log S_i);  out = mean_i loss_i
// ---------------------------------------------------------------------------
__global__ void finalize_kernel(float* __restrict__ out) {
    __shared__ float red[256];
    int t = threadIdx.x;
    float acc = 0.f;
    for (int i = t; i < NN; i += 256) {
        float lp = g_P[i] / g_cnt[i] - logf(g_S[i]);
        acc += g_mod[i & (BB - 1)] * lp;
    }
    red[t] = acc;
    __syncthreads();
#pragma unroll
    for (int s = 128; s > 0; s >>= 1) {
        if (t < s) red[t] += red[t + s];
        __syncthreads();
    }
    if (t == 0) out[0] = -red[0] / (float)NN;
}

// ---------------------------------------------------------------------------
extern "C" void kernel_launch(void* const* d_in, const int* in_sizes, int n_in,
                              void* d_out, int out_size) {
    const float* feats  = (const float*)d_in[0];   // [B, V, D]
    const float* preds  = (const float*)d_in[1];   // [B, C]
    const int*   labels = (const int*)d_in[2];     // [B]
    float* out = (float*)d_out;

    cudaFuncSetAttribute(main_kernel, cudaFuncAttributeMaxDynamicSharedMemorySize, K2_SMEM);

    norm_kernel<<<NN / 8, 256>>>(feats);           // 8 rows (warps) per block
    mod_kernel<<<BB, 128>>>(preds, labels);
    main_kernel<<<dim3(NN / 64, 4), 256, K2_SMEM>>>(labels);
    finalize_kernel<<<1, 256>>>(out);
}

// round 2
// speedup vs baseline: 1.6246x; 1.6246x over previous
#include <cuda_runtime.h>
#include <cuda_bf16.h>
#include <math.h>

// Problem constants (fixed shapes)
#define NN   4096      // N = V*B
#define BB   2048      // batch
#define VV   2         // views
#define DD   256       // feature dim
#define CC   1000      // classes
#define TEMP 0.07f

// Scratch (no cudaMalloc allowed)
__device__ float g_cf[NN * DD];   // normalized, view-major stacked features [N, D]
__device__ float g_mod[BB];       // focal modulation per sample
__device__ float g_S[NN];         // sum exp(l - M) over j != i
__device__ float g_P[NN];         // sum over positives of (l - M)
__device__ float g_cnt[NN];       // positive counts

// ---------------------------------------------------------------------------
// K0: normalize rows + view-major restack + zero accumulators
// features [B, V, D] -> g_cf[v*B + b][:]
// one warp per output row
// ---------------------------------------------------------------------------
__global__ void norm_kernel(const float* __restrict__ feats) {
    int gw   = (blockIdx.x * blockDim.x + threadIdx.x) >> 5;
    int lane = threadIdx.x & 31;
    if (gw >= NN) return;
    int b = gw & (BB - 1);
    int v = gw >> 11;

    const float4* src = reinterpret_cast<const float4*>(feats + (size_t)(b * VV + v) * DD);
    float4 x0 = src[lane];
    float4 x1 = src[lane + 32];

    float ss = x0.x * x0.x + x0.y * x0.y + x0.z * x0.z + x0.w * x0.w
             + x1.x * x1.x + x1.y * x1.y + x1.z * x1.z + x1.w * x1.w;
#pragma unroll
    for (int o = 16; o > 0; o >>= 1) ss += __shfl_xor_sync(0xffffffffu, ss, o);
    float inv = rsqrtf(ss);

    float4 y0 = make_float4(x0.x * inv, x0.y * inv, x0.z * inv, x0.w * inv);
    float4 y1 = make_float4(x1.x * inv, x1.y * inv, x1.z * inv, x1.w * inv);
    float4* dst = reinterpret_cast<float4*>(g_cf + (size_t)gw * DD);
    dst[lane]      = y0;
    dst[lane + 32] = y1;

    if (lane == 0) {   // zero accumulators every replay (graph-safe)
        g_S[gw] = 0.f; g_P[gw] = 0.f; g_cnt[gw] = 0.f;
    }
}

// ---------------------------------------------------------------------------
// K1: focal modulation per sample: mod = (1 - exp(log_softmax(preds)[label]))^2
// one block (128 threads) per sample b
// ---------------------------------------------------------------------------
__device__ __forceinline__ float warp_max(float v) {
#pragma unroll
    for (int o = 16; o > 0; o >>= 1) v = fmaxf(v, __shfl_xor_sync(0xffffffffu, v, o));
    return v;
}
__device__ __forceinline__ float warp_sum(float v) {
#pragma unroll
    for (int o = 16; o > 0; o >>= 1) v += __shfl_xor_sync(0xffffffffu, v, o);
    return v;
}

__global__ void mod_kernel(const float* __restrict__ preds, const int* __restrict__ labels) {
    __shared__ float sh4[4];
    int b = blockIdx.x, t = threadIdx.x, lane = t & 31, w = t >> 5;
    const float* row = preds + (size_t)b * CC;

    float mx = -1e30f;
    for (int c = t; c < CC; c += 128) mx = fmaxf(mx, row[c]);
    mx = warp_max(mx);
    if (lane == 0) sh4[w] = mx;
    __syncthreads();
    mx = fmaxf(fmaxf(sh4[0], sh4[1]), fmaxf(sh4[2], sh4[3]));
    __syncthreads();

    float s = 0.f;
    for (int c = t; c < CC; c += 128) s += __expf(row[c] - mx);
    s = warp_sum(s);
    if (lane == 0) sh4[w] = s;
    __syncthreads();

    if (t == 0) {
        float ssum = sh4[0] + sh4[1] + sh4[2] + sh4[3];
        float nll  = row[labels[b]] - mx - logf(ssum);  // log p_t
        float pt   = __expf(nll);
        float om   = 1.f - pt;
        g_mod[b]   = om * om;    // GAMMA = 2
    }
}

// ---------------------------------------------------------------------------
// K2: fused similarity GEMM + row reductions.
// Block = 64 rows x 1024-column strip. Grid (64, 4). 256 threads.
// Shared tiles stored k-major: As[256][68], Bs[64][68] (pad=4 floats).
// Microtile 4x4 per thread: per-k = 2x LDS.128 + 16 FFMA.
// Shift M = 1/T applied analytically (cancels exactly vs reference's row max).
// ---------------------------------------------------------------------------
#define WPAD 68
#define K2_SMEM ((256 * WPAD + 64 * WPAD) * 4)

__global__ void __launch_bounds__(256) main_kernel(const int* __restrict__ labels) {
    extern __shared__ float sh[];
    float* As = sh;                 // [256][WPAD] k-major, full D for 64 rows
    float* Bs = sh + 256 * WPAD;    // [64][WPAD]  k-major, BK=64 chunk for 64 cols
    __shared__ float sS[64], sP[64], sC[64];
    __shared__ int   cl[64];

    const int tid = threadIdx.x;
    const int tr = tid >> 4;        // 0..15 -> rows tr*4..tr*4+3
    const int tc = tid & 15;        // 0..15 -> cols tc*4..tc*4+3
    const int i0 = blockIdx.x * 64;
    const int jbase = blockIdx.y * 1024;

    if (tid < 64) { sS[tid] = 0.f; sP[tid] = 0.f; sC[tid] = 0.f; }

    // Fill As (once): rows i0..i0+63, all 256 k, transposed to k-major.
    {
        int r   = tid >> 2;
        int kq0 = tid & 3;
        const float4* src = reinterpret_cast<const float4*>(g_cf + (size_t)(i0 + r) * DD);
#pragma unroll
        for (int it = 0; it < 16; ++it) {
            int kq = kq0 + (it << 2);
            float4 vv = src[kq];
            int kb = kq << 2;
            As[(kb + 0) * WPAD + r] = vv.x;
            As[(kb + 1) * WPAD + r] = vv.y;
            As[(kb + 2) * WPAD + r] = vv.z;
            As[(kb + 3) * WPAD + r] = vv.w;
        }
    }

    int rl[4];
#pragma unroll
    for (int m = 0; m < 4; ++m) rl[m] = labels[(i0 + tr * 4 + m) & (BB - 1)];

    float s_acc[4] = {0.f, 0.f, 0.f, 0.f};
    float p_acc[4] = {0.f, 0.f, 0.f, 0.f};
    float c_acc[4] = {0.f, 0.f, 0.f, 0.f};

    const float invT = 1.0f / TEMP;

    for (int jt = 0; jt < 16; ++jt) {
        const int j0 = jbase + jt * 64;
        float acc[4][4];
#pragma unroll
        for (int m = 0; m < 4; ++m)
#pragma unroll
            for (int n = 0; n < 4; ++n) acc[m][n] = 0.f;

        for (int kc = 0; kc < 4; ++kc) {
            __syncthreads();
            // fill Bs chunk: cols j0..j0+63, k in [kc*64, kc*64+64)
            {
                int c   = tid >> 2;
                int kq0 = tid & 3;
                const float4* src = reinterpret_cast<const float4*>(
                    g_cf + (size_t)(j0 + c) * DD + kc * 64);
#pragma unroll
                for (int it = 0; it < 4; ++it) {
                    int kq = kq0 + (it << 2);
                    float4 vv = src[kq];
                    int kb = kq << 2;
                    Bs[(kb + 0) * WPAD + c] = vv.x;
                    Bs[(kb + 1) * WPAD + c] = vv.y;
                    Bs[(kb + 2) * WPAD + c] = vv.z;
                    Bs[(kb + 3) * WPAD + c] = vv.w;
                }
            }
            if (kc == 0 && tid < 64) cl[tid] = labels[(j0 + tid) & (BB - 1)];
            __syncthreads();

            const float* Ab = As + kc * 64 * WPAD;
#pragma unroll 8
            for (int k = 0; k < 64; ++k) {
                float4 a = *reinterpret_cast<const float4*>(Ab + k * WPAD + tr * 4);
                float4 b = *reinterpret_cast<const float4*>(Bs + k * WPAD + tc * 4);
                acc[0][0] += a.x * b.x; acc[0][1] += a.x * b.y;
                acc[0][2] += a.x * b.z; acc[0][3] += a.x * b.w;
                acc[1][0] += a.y * b.x; acc[1][1] += a.y * b.y;
                acc[1][2] += a.y * b.z; acc[1][3] += a.y * b.w;
                acc[2][0] += a.z * b.x; acc[2][1] += a.z * b.y;
                acc[2][2] += a.z * b.z; acc[2][3] += a.z * b.w;
                acc[3][0] += a.w * b.x; acc[3][1] += a.w * b.y;
                acc[3][2] += a.w * b.z; acc[3][3] += a.w * b.w;
            }
        }

        // Epilogue for this 64x64 tile: exp-sum / masked-logit-sum / counts
#pragma unroll
        for (int m = 0; m < 4; ++m) {
            const int i = i0 + tr * 4 + m;
#pragma unroll
            for (int n = 0; n < 4; ++n) {
                const int j = j0 + tc * 4 + n;
                float l = acc[m][n] * invT - invT;   // logits - M, M = 1/T
                if (i != j) {
                    s_acc[m] += __expf(l);
                    if (rl[m] == cl[tc * 4 + n]) { p_acc[m] += l; c_acc[m] += 1.f; }
                }
            }
        }
    }

    // Cross-thread (tc) reduction per row via shared atomics, then one global
    // atomic per row per block (4 column-strip blocks contribute per row).
#pragma unroll
    for (int m = 0; m < 4; ++m) {
        atomicAdd(&sS[tr * 4 + m], s_acc[m]);
        atomicAdd(&sP[tr * 4 + m], p_acc[m]);
        atomicAdd(&sC[tr * 4 + m], c_acc[m]);
    }
    __syncthreads();
    if (tid < 64) {
        atomicAdd(&g_S[i0 + tid],   sS[tid]);
        atomicAdd(&g_P[i0 + tid],   sP[tid]);
        atomicAdd(&g_cnt[i0 + tid], sC[tid]);
    }
}

// ---------------------------------------------------------------------------
// K3: per-row loss + mean
// loss_i = -mod[i%B] * (P_i/cnt_i - log S_i);  out = mean_i loss_i
// ---------------------------------------------------------------------------
__global__ void finalize_kernel(float* __restrict__ out) {
    __shared__ float red[256];
    int t = threadIdx.x;
    float acc = 0.f;
    for (int i = t; i < NN; i += 256) {
        float lp = g_P[i] / g_cnt[i] - logf(g_S[i]);
        acc += g_mod[i & (BB - 1)] * lp;
    }
    red[t] = acc;
    __syncthreads();
#pragma unroll
    for (int s = 128; s > 0; s >>= 1) {
        if (t < s) red[t] += red[t + s];
        __syncthreads();
    }
    if (t == 0) out[0] = -red[0] / (float)NN;
}

// ---------------------------------------------------------------------------
extern "C" void kernel_launch(void* const* d_in, const int* in_sizes, int n_in,
                              void* d_out, int out_size) {
    const float* feats  = (const float*)d_in[0];   // [B, V, D]
    const float* preds  = (const float*)d_in[1];   // [B, C]
    const int*   labels = (const int*)d_in[2];     // [B]
    float* out = (float*)d_out;

    cudaFuncSetAttribute(main_kernel, cudaFuncAttributeMaxDynamicSharedMemorySize, K2_SMEM);

    norm_kernel<<<NN / 8, 256>>>(feats);           // 8 rows (warps) per block
    mod_kernel<<<BB, 128>>>(preds, labels);
    main_kernel<<<dim3(NN / 64, 4), 256, K2_SMEM>>>(labels);
    finalize_kernel<<<1, 256>>>(out);
}